// round 15
// baseline (speedup 1.0000x reference)
#include <cuda_runtime.h>
#include <stdint.h>

#define HH 1024
#define WW 1024
#define BB 8
#define NPIX (HH*WW)          // 1048576
#define NPAIR 16              // pair = img*8 + b (img-major)
#define H1BINS 1056
#define H1PAD 1060            // padded stride for replicated copies
#define H2BINS 4096
#define H3BINS 256
#define SROWS 16              // rows per block
#define NSEG 512              // segments per pair (64 blocks x 8 warps)
#define SEGCAP 2048           // worst case: 16 rows x 4 px x 32 lanes

__device__ unsigned long long g_cand[NPAIR][NSEG][SEGCAP];  // segments
__device__ unsigned int g_scount[NPAIR][NSEG];
__device__ unsigned int g_hist1[NPAIR][H1BINS];
__device__ unsigned int g_hist2[NPAIR][H2BINS];
__device__ unsigned int g_hist3[NPAIR][H3BINS];
__device__ double g_loss;
__device__ unsigned int g_sel1[NPAIR];
__device__ unsigned int g_sel2[NPAIR];
__device__ unsigned int g_krem[NPAIR];

// ---------------------------------------------------------------------------
// K0: zero accumulators (graph replays must be deterministic)
// ---------------------------------------------------------------------------
__global__ void k_zero() {
    int idx = blockIdx.x * blockDim.x + threadIdx.x;
    int stride = gridDim.x * blockDim.x;
    const int n1 = NPAIR * H1BINS;
    const int n2 = NPAIR * H2BINS;
    const int n3 = NPAIR * H3BINS;
    const int tot = n1 + n2 + n3;
    unsigned int* h1 = &g_hist1[0][0];
    unsigned int* h2 = &g_hist2[0][0];
    unsigned int* h3 = &g_hist3[0][0];
    for (int i = idx; i < tot; i += stride) {
        if (i < n1) h1[i] = 0;
        else if (i < n1 + n2) h2[i - n1] = 0;
        else h3[i - n1 - n2] = 0;
    }
    if (idx == 0) g_loss = 0.0;
}

// ---------------------------------------------------------------------------
// Row fetch with warp-shuffle edge exchange: 1 float4 per lane; lanes 0/31
// fetch the warp-boundary scalar. Zero padding at image borders.
// ---------------------------------------------------------------------------
__device__ __forceinline__ void load_row6_shfl(const float* __restrict__ img,
                                               int y, int vx, int lane,
                                               float* v) {
    const float* row = img + ((size_t)y << 10);
    float4 c = __ldg((const float4*)row + vx);
    float left  = __shfl_up_sync(0xffffffffu, c.w, 1);
    float right = __shfl_down_sync(0xffffffffu, c.x, 1);
    if (lane == 0)  left  = (vx > 0)             ? __ldg(row + (vx << 2) - 1) : 0.f;
    if (lane == 31) right = (vx < (WW / 4 - 1))  ? __ldg(row + (vx << 2) + 4) : 0.f;
    v[0] = left; v[1] = c.x; v[2] = c.y; v[3] = c.z; v[4] = c.w; v[5] = right;
}

__device__ __forceinline__ float4 sobel_rows(const float* t, const float* m,
                                             const float* bo) {
    float g[4];
    #pragma unroll
    for (int i = 0; i < 4; i++) {
        float gx = (t[i + 2] - t[i]) + 2.f * (m[i + 2] - m[i]) + (bo[i + 2] - bo[i]);
        float gy = (t[i] - bo[i]) + 2.f * (t[i + 1] - bo[i + 1]) + (t[i + 2] - bo[i + 2]);
        g[i] = fabsf(gx) + fabsf(gy);
    }
    return make_float4(g[0], g[1], g[2], g[3]);
}

// ---------------------------------------------------------------------------
// K1: sobel(A,B,F) -> hist1 (4-way replicated) + loss. grid (64, BB).
// ---------------------------------------------------------------------------
__global__ void __launch_bounds__(256) k_sobel1(const float* __restrict__ A,
                                                const float* __restrict__ Bi,
                                                const float* __restrict__ F) {
    __shared__ unsigned int shA[4][H1PAD];
    __shared__ unsigned int shB[4][H1PAD];
    __shared__ float wsum[8];

    const int b = blockIdx.y;
    const int tid = threadIdx.x;               // vx = float4 column
    const int lane = tid & 31;
    const int rep = lane & 3;
    for (int i = tid; i < 4 * H1PAD; i += 256) {
        (&shA[0][0])[i] = 0u;
        (&shB[0][0])[i] = 0u;
    }
    __syncthreads();

    const size_t plane = (size_t)b * 3 * NPIX;
    const float* pa = A + plane;
    const float* pb = Bi + plane;
    const float* pf = F + plane;

    const int y0 = blockIdx.x * SROWS;

    float ta[6], ma[6], tb[6], mb[6], tf[6], mf[6];
    if (y0 > 0) {
        load_row6_shfl(pa, y0 - 1, tid, lane, ta);
        load_row6_shfl(pb, y0 - 1, tid, lane, tb);
        load_row6_shfl(pf, y0 - 1, tid, lane, tf);
    } else {
        #pragma unroll
        for (int i = 0; i < 6; i++) { ta[i] = 0.f; tb[i] = 0.f; tf[i] = 0.f; }
    }
    load_row6_shfl(pa, y0, tid, lane, ma);
    load_row6_shfl(pb, y0, tid, lane, mb);
    load_row6_shfl(pf, y0, tid, lane, mf);

    float lsum = 0.f;
    #pragma unroll 2
    for (int y = y0; y < y0 + SROWS; y++) {
        float ba[6], bb[6], bf[6];
        if (y + 1 < HH) {
            load_row6_shfl(pa, y + 1, tid, lane, ba);
            load_row6_shfl(pb, y + 1, tid, lane, bb);
            load_row6_shfl(pf, y + 1, tid, lane, bf);
        } else {
            #pragma unroll
            for (int i = 0; i < 6; i++) { ba[i] = 0.f; bb[i] = 0.f; bf[i] = 0.f; }
        }

        float4 ga = sobel_rows(ta, ma, ba);
        float4 gb = sobel_rows(tb, mb, bb);
        float4 gf = sobel_rows(tf, mf, bf);

        lsum += fabsf(gf.x - fmaxf(ga.x, gb.x));
        lsum += fabsf(gf.y - fmaxf(ga.y, gb.y));
        lsum += fabsf(gf.z - fmaxf(ga.z, gb.z));
        lsum += fabsf(gf.w - fmaxf(ga.w, gb.w));

        atomicAdd(&shA[rep][min(__float_as_uint(ga.x) >> 20, (unsigned)(H1BINS - 1))], 1u);
        atomicAdd(&shA[rep][min(__float_as_uint(ga.y) >> 20, (unsigned)(H1BINS - 1))], 1u);
        atomicAdd(&shA[rep][min(__float_as_uint(ga.z) >> 20, (unsigned)(H1BINS - 1))], 1u);
        atomicAdd(&shA[rep][min(__float_as_uint(ga.w) >> 20, (unsigned)(H1BINS - 1))], 1u);
        atomicAdd(&shB[rep][min(__float_as_uint(gb.x) >> 20, (unsigned)(H1BINS - 1))], 1u);
        atomicAdd(&shB[rep][min(__float_as_uint(gb.y) >> 20, (unsigned)(H1BINS - 1))], 1u);
        atomicAdd(&shB[rep][min(__float_as_uint(gb.z) >> 20, (unsigned)(H1BINS - 1))], 1u);
        atomicAdd(&shB[rep][min(__float_as_uint(gb.w) >> 20, (unsigned)(H1BINS - 1))], 1u);

        #pragma unroll
        for (int i = 0; i < 6; i++) {
            ta[i] = ma[i]; ma[i] = ba[i];
            tb[i] = mb[i]; mb[i] = bb[i];
            tf[i] = mf[i]; mf[i] = bf[i];
        }
    }

    // block-reduce loss
    float s = lsum;
    #pragma unroll
    for (int o = 16; o > 0; o >>= 1) s += __shfl_down_sync(0xffffffffu, s, o);
    if ((tid & 31) == 0) wsum[tid >> 5] = s;
    __syncthreads();
    if (tid < 8) {
        float t2 = wsum[tid];
        #pragma unroll
        for (int o = 4; o > 0; o >>= 1) t2 += __shfl_down_sync(0xffu, t2, o);
        if (tid == 0) atomicAdd(&g_loss, (double)t2);
    }

    __syncthreads();
    for (int i = tid; i < H1BINS; i += 256) {
        unsigned int ca = shA[0][i] + shA[1][i] + shA[2][i] + shA[3][i];
        unsigned int cb = shB[0][i] + shB[1][i] + shB[2][i] + shB[3][i];
        if (ca) atomicAdd(&g_hist1[b][i], ca);
        if (cb) atomicAdd(&g_hist1[BB + b][i], cb);
    }
}

// ---------------------------------------------------------------------------
// Block-wide exclusive scan (blockDim multiple of 32, <=1024)
// ---------------------------------------------------------------------------
__device__ __forceinline__ unsigned block_excl_scan(unsigned local,
                                                    unsigned* warp_sh) {
    const int lane = threadIdx.x & 31;
    const int wid = threadIdx.x >> 5;
    const int nwarps = blockDim.x >> 5;
    unsigned v = local;
    #pragma unroll
    for (int o = 1; o < 32; o <<= 1) {
        unsigned n = __shfl_up_sync(0xffffffffu, v, o);
        if (lane >= o) v += n;
    }
    if (lane == 31) warp_sh[wid] = v;
    __syncthreads();
    if (wid == 0) {
        unsigned w = (lane < nwarps) ? warp_sh[lane] : 0u;
        #pragma unroll
        for (int o = 1; o < 32; o <<= 1) {
            unsigned n = __shfl_up_sync(0xffffffffu, w, o);
            if (lane >= o) w += n;
        }
        if (lane < nwarps) warp_sh[lane] = w;
    }
    __syncthreads();
    unsigned base = (wid > 0) ? warp_sh[wid - 1] : 0u;
    return base + v - local;   // exclusive prefix
}

// ---------------------------------------------------------------------------
// K_SCAN1: one block per pair, find sel1/krem from hist1
// ---------------------------------------------------------------------------
__global__ void k_scan1(const int* __restrict__ thr) {
    __shared__ unsigned ws[32];
    const int p = blockIdx.x;
    const int tid = threadIdx.x;
    const unsigned k = (unsigned)thr[0];
    unsigned bins[4] = {0u, 0u, 0u, 0u};
    const int base = tid * 4;
    if (base < H1BINS) {
        uint4 v = *(const uint4*)&g_hist1[p][base];
        bins[0] = v.x; bins[1] = v.y; bins[2] = v.z; bins[3] = v.w;
    }
    unsigned local = bins[0] + bins[1] + bins[2] + bins[3];
    unsigned cum = block_excl_scan(local, ws);
    #pragma unroll
    for (int j = 0; j < 4; j++) {
        unsigned nb = cum + bins[j];
        if (cum < k && nb >= k) { g_sel1[p] = base + j; g_krem[p] = k - cum; }
        cum = nb;
    }
}

// ---------------------------------------------------------------------------
// K2: recompute sobel for ONE image; write provisional mask directly from
//     registers; compact candidates into per-warp segments (warp ballot);
//     inline sparse hist2. grid (64, BB, 2), 256 threads.
// ---------------------------------------------------------------------------
__global__ void __launch_bounds__(256) k_sobel2(const float* __restrict__ A,
                                                const float* __restrict__ Bi,
                                                float* __restrict__ out) {
    const int b = blockIdx.y;
    const int img = blockIdx.z;
    const int p = img * BB + b;
    const int tid = threadIdx.x;
    const int lane = tid & 31;
    const int wid = tid >> 5;
    const unsigned lml = (1u << lane) - 1u;
    const unsigned sel = g_sel1[p];

    const float* src = ((img == 0) ? A : Bi) + (size_t)b * 3 * NPIX;
    float* outp = out + 1 + (size_t)p * NPIX;
    unsigned long long* seg = g_cand[p][blockIdx.x * 8 + wid];
    unsigned wcnt = 0;                      // warp-uniform running count

    const int y0 = blockIdx.x * SROWS;

    float t[6], m[6];
    if (y0 > 0) {
        load_row6_shfl(src, y0 - 1, tid, lane, t);
    } else {
        #pragma unroll
        for (int i = 0; i < 6; i++) t[i] = 0.f;
    }
    load_row6_shfl(src, y0, tid, lane, m);

    #pragma unroll 2
    for (int y = y0; y < y0 + SROWS; y++) {
        float bo[6];
        if (y + 1 < HH) {
            load_row6_shfl(src, y + 1, tid, lane, bo);
        } else {
            #pragma unroll
            for (int i = 0; i < 6; i++) bo[i] = 0.f;
        }

        float4 g4 = sobel_rows(t, m, bo);
        unsigned uu[4] = {__float_as_uint(g4.x), __float_as_uint(g4.y),
                          __float_as_uint(g4.z), __float_as_uint(g4.w)};
        const unsigned pixbase = (unsigned)(y << 10) + (tid << 2);
        float* rout = outp + pixbase;

        // provisional mask: direct scalar streaming stores
        #pragma unroll
        for (int e = 0; e < 4; e++)
            __stcs(rout + e, ((uu[e] >> 20) > sel) ? 1.0f : 0.0f);

        // per-warp segment compaction + inline hist2
        #pragma unroll
        for (int e = 0; e < 4; e++) {
            const unsigned u = uu[e];
            const bool match = ((u >> 20) == sel);
            unsigned bal = __ballot_sync(0xffffffffu, match);
            if (match) {
                unsigned rank = __popc(bal & lml);
                seg[wcnt + rank] =
                    ((unsigned long long)(u & 0xFFFFFu) << 20)
                    | (unsigned long long)(pixbase + e);
                atomicAdd(&g_hist2[p][(u >> 8) & 0xFFFu], 1u);
            }
            wcnt += __popc(bal);
        }

        #pragma unroll
        for (int i = 0; i < 6; i++) { t[i] = m[i]; m[i] = bo[i]; }
    }

    if (lane == 0) g_scount[p][blockIdx.x * 8 + wid] = wcnt;
}

// ---------------------------------------------------------------------------
// K_SCAN2: one block per pair, find sel2/krem from hist2
// ---------------------------------------------------------------------------
__global__ void k_scan2() {
    __shared__ unsigned ws[32];
    const int p = blockIdx.x;
    const int tid = threadIdx.x;
    const unsigned k = g_krem[p];
    const int base = tid * 4;
    uint4 v = *(const uint4*)&g_hist2[p][base];
    unsigned bins[4] = {v.x, v.y, v.z, v.w};
    unsigned local = bins[0] + bins[1] + bins[2] + bins[3];
    unsigned cum = block_excl_scan(local, ws);
    #pragma unroll
    for (int j = 0; j < 4; j++) {
        unsigned nb = cum + bins[j];
        if (cum < k && nb >= k) { g_sel2[p] = base + j; g_krem[p] = k - cum; }
        cum = nb;
    }
}

// ---------------------------------------------------------------------------
// K_HIST3C: hist of bits[7:0] over candidates matching sel2, segments.
// grid (64, NPAIR): block handles 8 segments.
// ---------------------------------------------------------------------------
__global__ void k_hist3c() {
    __shared__ unsigned int h[H3BINS];
    const int p = blockIdx.y;
    const int tid = threadIdx.x;
    for (int i = tid; i < H3BINS; i += 256) h[i] = 0u;
    __syncthreads();
    const unsigned sel2 = g_sel2[p];
    for (int s = 0; s < 8; s++) {
        const int sidx = blockIdx.x * 8 + s;
        const unsigned cnt = g_scount[p][sidx];
        const unsigned long long* seg = g_cand[p][sidx];
        for (unsigned i = tid; i < cnt; i += 256) {
            unsigned low = (unsigned)(seg[i] >> 20);
            if ((low >> 8) == sel2) atomicAdd(&h[low & 0xFFu], 1u);
        }
    }
    __syncthreads();
    for (int i = tid; i < H3BINS; i += 256) {
        unsigned cc = h[i];
        if (cc) atomicAdd(&g_hist3[p][i], cc);
    }
}

// ---------------------------------------------------------------------------
// K_FIX: inline scan3 (256 bins) then resolve candidate pixels; write loss.
// grid (64, NPAIR), 256 threads.
// ---------------------------------------------------------------------------
__global__ void k_fix(float* __restrict__ out) {
    __shared__ unsigned ws[32];
    __shared__ unsigned sh_kl;
    const int p = blockIdx.y;
    const int tid = threadIdx.x;
    const unsigned k = g_krem[p];
    const unsigned sel2 = g_sel2[p];

    // inline scan3: 256 threads, 1 bin each
    {
        unsigned bin = g_hist3[p][tid];
        unsigned cum = block_excl_scan(bin, ws);
        if (cum < k && cum + bin >= k) sh_kl = (sel2 << 8) | (unsigned)tid;
    }
    __syncthreads();
    const unsigned kl = sh_kl;

    const size_t obase = 1 + (size_t)p * NPIX;
    for (int s = 0; s < 8; s++) {
        const int sidx = blockIdx.x * 8 + s;
        const unsigned cnt = g_scount[p][sidx];
        const unsigned long long* seg = g_cand[p][sidx];
        for (unsigned i = tid; i < cnt; i += 256) {
            unsigned long long c = seg[i];
            unsigned low = (unsigned)(c >> 20);
            out[obase + (unsigned)(c & 0xFFFFFu)] = (low >= kl) ? 1.0f : 0.0f;
        }
    }
    if (p == 0 && blockIdx.x == 0 && tid == 0)
        out[0] = (float)(g_loss / 8388608.0);
}

// ---------------------------------------------------------------------------
extern "C" void kernel_launch(void* const* d_in, const int* in_sizes, int n_in,
                              void* d_out, int out_size) {
    const float* A   = (const float*)d_in[0];
    const float* Bi  = (const float*)d_in[1];
    const float* F   = (const float*)d_in[2];
    const int*   thr = (const int*)d_in[3];
    float* out = (float*)d_out;

    k_zero<<<64, 256>>>();
    k_sobel1<<<dim3(HH / SROWS, BB), 256>>>(A, Bi, F);     // (64, 8)
    k_scan1<<<NPAIR, 512>>>(thr);
    k_sobel2<<<dim3(HH / SROWS, BB, 2), 256>>>(A, Bi, out);// (64, 8, 2)
    k_scan2<<<NPAIR, 1024>>>();
    k_hist3c<<<dim3(64, NPAIR), 256>>>();
    k_fix<<<dim3(64, NPAIR), 256>>>(out);
}

// round 16
// speedup vs baseline: 1.6345x; 1.6345x over previous
#include <cuda_runtime.h>
#include <stdint.h>

#define HH 1024
#define WW 1024
#define BB 8
#define NPIX (HH*WW)          // 1048576
#define NPAIR 16              // pair = img*8 + b (img-major)
#define H1BINS 1056
#define H2BINS 4096
#define H3BINS 256
#define SROWS 16              // rows per sobel block
#define CANDCAP (NPIX / 8)    // deferred candidates per pair (ample)

__device__ float g_scr[2][BB][NPIX];                 // gA, gB (64 MB)
__device__ unsigned int g_cand[NPAIR][CANDCAP];      // (low8<<24)|idx (deferred)
__device__ unsigned int g_ccount[NPAIR];
__device__ unsigned int g_hist1[NPAIR][H1BINS];
__device__ unsigned int g_hist2[NPAIR][H2BINS];
__device__ unsigned int g_hist3[NPAIR][H3BINS];
__device__ double g_loss;
__device__ unsigned int g_sel1[NPAIR];
__device__ unsigned int g_sel2[NPAIR];
__device__ unsigned int g_krem[NPAIR];

// ---------------------------------------------------------------------------
// K0: zero accumulators (graph replays must be deterministic)
// ---------------------------------------------------------------------------
__global__ void k_zero() {
    int idx = blockIdx.x * blockDim.x + threadIdx.x;
    int stride = gridDim.x * blockDim.x;
    const int n1 = NPAIR * H1BINS;
    const int n2 = NPAIR * H2BINS;
    const int n3 = NPAIR * H3BINS;
    const int tot = n1 + n2 + n3;
    unsigned int* h1 = &g_hist1[0][0];
    unsigned int* h2 = &g_hist2[0][0];
    unsigned int* h3 = &g_hist3[0][0];
    for (int i = idx; i < tot; i += stride) {
        if (i < n1) h1[i] = 0;
        else if (i < n1 + n2) h2[i - n1] = 0;
        else h3[i - n1 - n2] = 0;
    }
    if (idx < NPAIR) g_ccount[idx] = 0u;
    if (idx == 0) g_loss = 0.0;
}

// ---------------------------------------------------------------------------
// Row fetch: floats x-1..x+4 for the 4 pixels at x = 4*vx, zero at borders
// ---------------------------------------------------------------------------
__device__ __forceinline__ void load_row6(const float* __restrict__ img,
                                          int y, int vx, float* v) {
    const float* row = img + ((size_t)y << 10);
    float4 c = __ldcs((const float4*)row + vx);
    v[0] = (vx > 0) ? __ldcs(row + (vx << 2) - 1) : 0.f;
    v[1] = c.x; v[2] = c.y; v[3] = c.z; v[4] = c.w;
    v[5] = (vx < (WW / 4 - 1)) ? __ldcs(row + (vx << 2) + 4) : 0.f;
}

__device__ __forceinline__ float4 sobel_rows(const float* t, const float* m,
                                             const float* bo) {
    float g[4];
    #pragma unroll
    for (int i = 0; i < 4; i++) {
        float gx = (t[i + 2] - t[i]) + 2.f * (m[i + 2] - m[i]) + (bo[i + 2] - bo[i]);
        float gy = (t[i] - bo[i]) + 2.f * (t[i + 1] - bo[i + 1]) + (t[i + 2] - bo[i + 2]);
        g[i] = fabsf(gx) + fabsf(gy);
    }
    return make_float4(g[0], g[1], g[2], g[3]);
}

// ---------------------------------------------------------------------------
// K1: fused sobel(A,B,F) + scratch store + loss + hist1 (exact R5 version)
// grid (64, BB), 256 threads
// ---------------------------------------------------------------------------
__global__ void k_sobel(const float* __restrict__ A,
                        const float* __restrict__ Bi,
                        const float* __restrict__ F) {
    __shared__ unsigned int shA[H1BINS];
    __shared__ unsigned int shB[H1BINS];
    __shared__ float wsum[8];

    const int b = blockIdx.y;
    const int tid = threadIdx.x;               // vx = float4 column
    for (int i = tid; i < H1BINS; i += 256) { shA[i] = 0u; shB[i] = 0u; }
    __syncthreads();

    const size_t plane = (size_t)b * 3 * NPIX;
    const float* pa = A + plane;
    const float* pb = Bi + plane;
    const float* pf = F + plane;
    float4* outA = (float4*)g_scr[0][b];
    float4* outB = (float4*)g_scr[1][b];

    const int y0 = blockIdx.x * SROWS;

    float ta[6], ma[6], tb[6], mb[6], tf[6], mf[6];
    if (y0 > 0) {
        load_row6(pa, y0 - 1, tid, ta);
        load_row6(pb, y0 - 1, tid, tb);
        load_row6(pf, y0 - 1, tid, tf);
    } else {
        #pragma unroll
        for (int i = 0; i < 6; i++) { ta[i] = 0.f; tb[i] = 0.f; tf[i] = 0.f; }
    }
    load_row6(pa, y0, tid, ma);
    load_row6(pb, y0, tid, mb);
    load_row6(pf, y0, tid, mf);

    float lsum = 0.f;
    #pragma unroll 2
    for (int y = y0; y < y0 + SROWS; y++) {
        float ba[6], bb[6], bf[6];
        if (y + 1 < HH) {
            load_row6(pa, y + 1, tid, ba);
            load_row6(pb, y + 1, tid, bb);
            load_row6(pf, y + 1, tid, bf);
        } else {
            #pragma unroll
            for (int i = 0; i < 6; i++) { ba[i] = 0.f; bb[i] = 0.f; bf[i] = 0.f; }
        }

        float4 ga = sobel_rows(ta, ma, ba);
        float4 gb = sobel_rows(tb, mb, bb);
        float4 gf = sobel_rows(tf, mf, bf);

        const int vec = (y << 8) + tid;
        outA[vec] = ga;
        outB[vec] = gb;

        lsum += fabsf(gf.x - fmaxf(ga.x, gb.x));
        lsum += fabsf(gf.y - fmaxf(ga.y, gb.y));
        lsum += fabsf(gf.z - fmaxf(ga.z, gb.z));
        lsum += fabsf(gf.w - fmaxf(ga.w, gb.w));

        atomicAdd(&shA[min(__float_as_uint(ga.x) >> 20, (unsigned)(H1BINS - 1))], 1u);
        atomicAdd(&shA[min(__float_as_uint(ga.y) >> 20, (unsigned)(H1BINS - 1))], 1u);
        atomicAdd(&shA[min(__float_as_uint(ga.z) >> 20, (unsigned)(H1BINS - 1))], 1u);
        atomicAdd(&shA[min(__float_as_uint(ga.w) >> 20, (unsigned)(H1BINS - 1))], 1u);
        atomicAdd(&shB[min(__float_as_uint(gb.x) >> 20, (unsigned)(H1BINS - 1))], 1u);
        atomicAdd(&shB[min(__float_as_uint(gb.y) >> 20, (unsigned)(H1BINS - 1))], 1u);
        atomicAdd(&shB[min(__float_as_uint(gb.z) >> 20, (unsigned)(H1BINS - 1))], 1u);
        atomicAdd(&shB[min(__float_as_uint(gb.w) >> 20, (unsigned)(H1BINS - 1))], 1u);

        #pragma unroll
        for (int i = 0; i < 6; i++) {
            ta[i] = ma[i]; ma[i] = ba[i];
            tb[i] = mb[i]; mb[i] = bb[i];
            tf[i] = mf[i]; mf[i] = bf[i];
        }
    }

    // block-reduce loss
    float s = lsum;
    #pragma unroll
    for (int o = 16; o > 0; o >>= 1) s += __shfl_down_sync(0xffffffffu, s, o);
    if ((tid & 31) == 0) wsum[tid >> 5] = s;
    __syncthreads();
    if (tid < 8) {
        float t2 = wsum[tid];
        #pragma unroll
        for (int o = 4; o > 0; o >>= 1) t2 += __shfl_down_sync(0xffu, t2, o);
        if (tid == 0) atomicAdd(&g_loss, (double)t2);
    }

    __syncthreads();
    for (int i = tid; i < H1BINS; i += 256) {
        unsigned int ca = shA[i], cb = shB[i];
        if (ca) atomicAdd(&g_hist1[b][i], ca);
        if (cb) atomicAdd(&g_hist1[BB + b][i], cb);
    }
}

// ---------------------------------------------------------------------------
// Block-wide exclusive scan (blockDim multiple of 32, <=1024)
// ---------------------------------------------------------------------------
__device__ __forceinline__ unsigned block_excl_scan(unsigned local,
                                                    unsigned* warp_sh) {
    const int lane = threadIdx.x & 31;
    const int wid = threadIdx.x >> 5;
    const int nwarps = blockDim.x >> 5;
    unsigned v = local;
    #pragma unroll
    for (int o = 1; o < 32; o <<= 1) {
        unsigned n = __shfl_up_sync(0xffffffffu, v, o);
        if (lane >= o) v += n;
    }
    if (lane == 31) warp_sh[wid] = v;
    __syncthreads();
    if (wid == 0) {
        unsigned w = (lane < nwarps) ? warp_sh[lane] : 0u;
        #pragma unroll
        for (int o = 1; o < 32; o <<= 1) {
            unsigned n = __shfl_up_sync(0xffffffffu, w, o);
            if (lane >= o) w += n;
        }
        if (lane < nwarps) warp_sh[lane] = w;
    }
    __syncthreads();
    unsigned base = (wid > 0) ? warp_sh[wid - 1] : 0u;
    return base + v - local;   // exclusive prefix
}

// ---------------------------------------------------------------------------
// K_SCAN1: one block per pair, find sel1/krem from hist1
// ---------------------------------------------------------------------------
__global__ void k_scan1(const int* __restrict__ thr) {
    __shared__ unsigned ws[32];
    const int p = blockIdx.x;
    const int tid = threadIdx.x;
    const unsigned k = (unsigned)thr[0];
    unsigned bins[4] = {0u, 0u, 0u, 0u};
    const int base = tid * 4;
    if (base < H1BINS) {
        uint4 v = *(const uint4*)&g_hist1[p][base];
        bins[0] = v.x; bins[1] = v.y; bins[2] = v.z; bins[3] = v.w;
    }
    unsigned local = bins[0] + bins[1] + bins[2] + bins[3];
    unsigned cum = block_excl_scan(local, ws);
    #pragma unroll
    for (int j = 0; j < 4; j++) {
        unsigned nb = cum + bins[j];
        if (cum < k && nb >= k) { g_sel1[p] = base + j; g_krem[p] = k - cum; }
        cum = nb;
    }
}

// ---------------------------------------------------------------------------
// K_HIST2: streaming hist of bits[19:8] for values matching sel1 (R5 exact,
// measured 19.0us). 4 independent loads per thread, 4096 blocks.
// ---------------------------------------------------------------------------
__global__ void __launch_bounds__(256) k_hist2() {
    const float4* __restrict__ src = (const float4*)&g_scr[0][0][0];
    const unsigned idx = blockIdx.x * 256 + threadIdx.x;
    const unsigned stride = 4096u * 256u;   // 1M threads, 4 vec each
    float4 v[4];
    #pragma unroll
    for (int j = 0; j < 4; j++) v[j] = src[idx + j * stride];
    #pragma unroll
    for (int j = 0; j < 4; j++) {
        const unsigned p = (idx + j * stride) >> 18;
        const unsigned sel = g_sel1[p];
        unsigned u;
        u = __float_as_uint(v[j].x); if ((u >> 20) == sel) atomicAdd(&g_hist2[p][(u >> 8) & 0xFFFu], 1u);
        u = __float_as_uint(v[j].y); if ((u >> 20) == sel) atomicAdd(&g_hist2[p][(u >> 8) & 0xFFFu], 1u);
        u = __float_as_uint(v[j].z); if ((u >> 20) == sel) atomicAdd(&g_hist2[p][(u >> 8) & 0xFFFu], 1u);
        u = __float_as_uint(v[j].w); if ((u >> 20) == sel) atomicAdd(&g_hist2[p][(u >> 8) & 0xFFFu], 1u);
    }
}

// ---------------------------------------------------------------------------
// K_SCAN2: one block per pair, find sel2/krem from hist2
// ---------------------------------------------------------------------------
__global__ void k_scan2() {
    __shared__ unsigned ws[32];
    const int p = blockIdx.x;
    const int tid = threadIdx.x;
    const unsigned k = g_krem[p];
    const int base = tid * 4;
    uint4 v = *(const uint4*)&g_hist2[p][base];
    unsigned bins[4] = {v.x, v.y, v.z, v.w};
    unsigned local = bins[0] + bins[1] + bins[2] + bins[3];
    unsigned cum = block_excl_scan(local, ws);
    #pragma unroll
    for (int j = 0; j < 4; j++) {
        unsigned nb = cum + bins[j];
        if (cum < k && nb >= k) { g_sel2[p] = base + j; g_krem[p] = k - cum; }
        cum = nb;
    }
}

// ---------------------------------------------------------------------------
// K_PASS3: one streaming pass over scratch (structure = R12 pass2, 26.5us).
//   mask decided for all but (sel1,sel2)-matches (deferred, ~hundreds):
//     top>sel1 -> 1; top<sel1 -> 0; top==sel1: mid>sel2 ->1, mid<sel2 ->0,
//     mid==sel2 -> 0 now, deferred fix + inline hist3.
// grid (512, NPAIR), 256 threads, 2 uint4 per thread.
// ---------------------------------------------------------------------------
__global__ void __launch_bounds__(256) k_pass3(float* __restrict__ out) {
    __shared__ float stage[2048];

    const int p = blockIdx.y;
    const int tid = threadIdx.x;
    const unsigned sel1 = g_sel1[p];
    const unsigned sel2 = g_sel2[p];
    const unsigned pref = (sel1 << 12) | sel2;   // top 24 bits match

    const uint4* __restrict__ src =
        (const uint4*)&g_scr[0][0][0] + (size_t)p * (NPIX / 4);
    const unsigned v0 = blockIdx.x * 512 + tid;
    const unsigned v1 = v0 + 256;
    uint4 d0 = src[v0];
    uint4 d1 = src[v1];
    unsigned u0[4] = {d0.x, d0.y, d0.z, d0.w};
    unsigned u1[4] = {d1.x, d1.y, d1.z, d1.w};

    #pragma unroll
    for (int e = 0; e < 4; e++) {
        unsigned a = u0[e], bv = u1[e];
        // decided mask: strictly greater than the (sel1,sel2) 24-bit prefix
        stage[(tid << 2) + e]         = ((a >> 8) > pref) ? 1.0f : 0.0f;
        stage[((256 + tid) << 2) + e] = ((bv >> 8) > pref) ? 1.0f : 0.0f;
        if ((a >> 8) == pref) {      // deferred (rare)
            unsigned pos = atomicAdd(&g_ccount[p], 1u);
            g_cand[p][pos] = ((a & 0xFFu) << 24) | (((v0 << 2) + e) & 0xFFFFFFu);
            atomicAdd(&g_hist3[p][a & 0xFFu], 1u);
        }
        if ((bv >> 8) == pref) {
            unsigned pos = atomicAdd(&g_ccount[p], 1u);
            g_cand[p][pos] = ((bv & 0xFFu) << 24) | (((v1 << 2) + e) & 0xFFFFFFu);
            atomicAdd(&g_hist3[p][bv & 0xFFu], 1u);
        }
    }
    __syncthreads();

    // mask stores: out+1 misalignment -> aligned float4 at stage idx 3 mod 4
    const size_t obase = 1 + (size_t)p * NPIX + ((size_t)blockIdx.x << 11);
    #pragma unroll
    for (int s = tid; s < 511; s += 256) {
        float4 w = make_float4(stage[(s << 2) + 3], stage[(s << 2) + 4],
                               stage[(s << 2) + 5], stage[(s << 2) + 6]);
        __stcs((float4*)(out + obase + (s << 2) + 3), w);
    }
    if (tid < 3) out[obase + tid] = stage[tid];
    if (tid == 3) out[obase + 2047] = stage[2047];
}

// ---------------------------------------------------------------------------
// K_FIX: inline scan3 (256 bins) then resolve deferred pixels; write loss.
// grid NPAIR, 256 threads.
// ---------------------------------------------------------------------------
__global__ void k_fix(float* __restrict__ out) {
    __shared__ unsigned ws[32];
    __shared__ unsigned sh_kl;
    const int p = blockIdx.x;
    const int tid = threadIdx.x;
    const unsigned k = g_krem[p];

    // inline scan3: 256 threads, 1 bin each (kth low-8 within deferred set)
    {
        unsigned bin = g_hist3[p][tid];
        unsigned cum = block_excl_scan(bin, ws);
        if (cum < k && cum + bin >= k) sh_kl = (unsigned)tid;
    }
    __syncthreads();
    const unsigned kl = sh_kl;

    const unsigned cnt = g_ccount[p];
    const size_t obase = 1 + (size_t)p * NPIX;
    for (unsigned i = tid; i < cnt; i += 256) {
        unsigned c = g_cand[p][i];
        unsigned low = c >> 24;
        out[obase + (c & 0xFFFFFFu)] = (low >= kl) ? 1.0f : 0.0f;
    }
    if (p == 0 && tid == 0)
        out[0] = (float)(g_loss / 8388608.0);
}

// ---------------------------------------------------------------------------
extern "C" void kernel_launch(void* const* d_in, const int* in_sizes, int n_in,
                              void* d_out, int out_size) {
    const float* A   = (const float*)d_in[0];
    const float* Bi  = (const float*)d_in[1];
    const float* F   = (const float*)d_in[2];
    const int*   thr = (const int*)d_in[3];
    float* out = (float*)d_out;

    k_zero<<<64, 256>>>();
    k_sobel<<<dim3(HH / SROWS, BB), 256>>>(A, Bi, F);    // (64, 8)
    k_scan1<<<NPAIR, 512>>>(thr);
    k_hist2<<<4096, 256>>>();
    k_scan2<<<NPAIR, 1024>>>();
    k_pass3<<<dim3(NPIX / 8 / 256, NPAIR), 256>>>(out);  // (512, 16)
    k_fix<<<NPAIR, 256>>>(out);
}